// round 6
// baseline (speedup 1.0000x reference)
#include <cuda_runtime.h>
#include <cuda_bf16.h>
#include <math_constants.h>
#include <cstdint>

#define Bb 64
#define Ss 2048
#define Hh 1024
#define Aa 512

// ---------------- device scratch (no allocation allowed) --------------------
__device__ float g_C[Bb * Aa];
__device__ float g_sc0[Bb * Ss];
__device__ float g_sc1[Bb * Ss];
__device__ float g_opart[Bb * 16 * Hh];
__device__ __nv_bfloat16 g_Whi[Aa * Hh];
__device__ __nv_bfloat16 g_Wlo[Aa * Hh];

// ---------------- helpers ---------------------------------------------------
__device__ __forceinline__ uint32_t smem_u32(const void* p) {
    uint32_t a;
    asm("{ .reg .u64 t; cvta.to.shared.u64 t, %1; cvt.u32.u64 %0, t; }" : "=r"(a) : "l"(p));
    return a;
}
__device__ __forceinline__ void cp_async16(uint32_t dst, const void* src) {
    asm volatile("cp.async.cg.shared.global [%0], [%1], 16;" :: "r"(dst), "l"(src) : "memory");
}
__device__ __forceinline__ void cp_commit() {
    asm volatile("cp.async.commit_group;" ::: "memory");
}
__device__ __forceinline__ void ldmx4(uint32_t& r0, uint32_t& r1, uint32_t& r2, uint32_t& r3,
                                      uint32_t addr) {
    asm volatile("ldmatrix.sync.aligned.m8n8.x4.shared.b16 {%0,%1,%2,%3}, [%4];"
                 : "=r"(r0), "=r"(r1), "=r"(r2), "=r"(r3) : "r"(addr));
}
__device__ __forceinline__ void mma_bf16(float* d, const uint32_t* a, const uint32_t* b) {
    asm volatile(
        "mma.sync.aligned.m16n8k16.row.col.f32.bf16.bf16.f32 "
        "{%0,%1,%2,%3}, {%4,%5,%6,%7}, {%8,%9}, {%0,%1,%2,%3};"
        : "+f"(d[0]), "+f"(d[1]), "+f"(d[2]), "+f"(d[3])
        : "r"(a[0]), "r"(a[1]), "r"(a[2]), "r"(a[3]), "r"(b[0]), "r"(b[1]));
}

// smem: 3 stages of [Xhi 10240 | Xlo 10240 | Whi 20480 | Wlo 20480] (80B rows)
#define STG_SZ   61440
#define OFF_XLO  10240
#define OFF_WHI  20480
#define OFF_WLO  40960
#define OFF_SCP  184320           // 512 floats
#define OFF_CS   186368           // 256 floats
#define OFF_VS   187392           // 256 floats
#define SMEM_SZ  188416

// ---------------------------------------------------------------------------
// prep_w: split Wh (fp32 [512][1024]) into bf16 hi/lo planes, row-major.
// ---------------------------------------------------------------------------
__global__ void prep_w(const float* __restrict__ Wh) {
    int a = blockIdx.x;
    int t = threadIdx.x;
    float4 v = *(const float4*)(Wh + (size_t)a * 1024 + t * 4);
    union U { __nv_bfloat16 h[4]; uint2 u; };
    U hi, lo;
    float f[4] = {v.x, v.y, v.z, v.w};
#pragma unroll
    for (int e = 0; e < 4; e++) {
        hi.h[e] = __float2bfloat16(f[e]);
        lo.h[e] = __float2bfloat16(f[e] - __bfloat162float(hi.h[e]));
    }
    *(uint2*)(g_Whi + (size_t)a * 1024 + t * 4) = hi.u;
    *(uint2*)(g_Wlo + (size_t)a * 1024 + t * 4) = lo.u;
}

// ---------------------------------------------------------------------------
// ctx: C[b,a] = Wh_b[a] + x0@W0[a] + x1@W1[a] + x2@W2[a]
// ---------------------------------------------------------------------------
__global__ void ctx_kernel(const float* __restrict__ x0,
                           const float* __restrict__ x1,
                           const float* __restrict__ x2,
                           const float* __restrict__ W0,
                           const float* __restrict__ W1,
                           const float* __restrict__ W2,
                           const float* __restrict__ Whb) {
    __shared__ float xs[2048];
    int b = blockIdx.x;
    int t = threadIdx.x;
    xs[t]        = x0[b * 1024 + t];
    xs[t + 512]  = x0[b * 1024 + t + 512];
    xs[1024 + t] = x1[b * 512 + t];
    xs[1536 + t] = x2[b * 512 + t];
    __syncthreads();
    int a = t;
    float acc = Whb[a];
    const float4* w0 = (const float4*)(W0 + (size_t)a * 1024);
    const float4* xv = (const float4*)xs;
#pragma unroll 8
    for (int i = 0; i < 256; i++) {
        float4 w = w0[i]; float4 x = xv[i];
        acc += w.x * x.x + w.y * x.y + w.z * x.z + w.w * x.w;
    }
    const float4* w1 = (const float4*)(W1 + (size_t)a * 512);
    const float4* x1v = (const float4*)(xs + 1024);
#pragma unroll 8
    for (int i = 0; i < 128; i++) {
        float4 w = w1[i]; float4 x = x1v[i];
        acc += w.x * x.x + w.y * x.y + w.z * x.z + w.w * x.w;
    }
    const float4* w2 = (const float4*)(W2 + (size_t)a * 512);
    const float4* x2v = (const float4*)(xs + 1536);
#pragma unroll 8
    for (int i = 0; i < 128; i++) {
        float4 w = w2[i]; float4 x = x2v[i];
        acc += w.x * x.x + w.y * x.y + w.z * x.z + w.w * x.w;
    }
    g_C[b * Aa + a] = acc;
}

// ---------------------------------------------------------------------------
// scores_mma: fused scores, 3-stage pipeline, ONE barrier per k-chunk.
//   D[128 s,256 a] = X @ Wh^T (bf16x3); score[s] = sum_a relu(D+C)*V
// X is split fp32->bf16 hi/lo in-kernel (regs prefetched 1 iter ahead);
// W planes arrive via cp.async. grid (16 st, 2 ah, 64 b), 512 threads.
// ---------------------------------------------------------------------------
__global__ void __launch_bounds__(512, 1)
scores_mma(const float* __restrict__ X,
           const float* __restrict__ V,
           const int* __restrict__ lengths) {
    extern __shared__ char smem[];
    int st = blockIdx.x, ah = blockIdx.y, b = blockIdx.z;
    int len = lengths[b];
    int s0 = st * 128;
    if (s0 >= len) return;

    int tid = threadIdx.x;
    int wid = tid >> 5;
    int lane = tid & 31;
    int wm = wid >> 2;
    int wn = wid & 3;

    float* cs = (float*)(smem + OFF_CS);
    float* vs = (float*)(smem + OFF_VS);
    if (tid < 256) {
        cs[tid] = g_C[b * Aa + ah * 256 + tid];
        vs[tid] = V[ah * 256 + tid];
    }

    uint32_t sbase = smem_u32(smem);

    // ---- X mapping: 2 float4 per thread (128 rows x 32 cols fp32 per stage)
    int xrow0 = (tid * 2) >> 3;
    int xq0   = (tid * 2) & 7;
    int xrow1 = (tid * 2 + 1) >> 3;
    int xq1   = (tid * 2 + 1) & 7;
    const float* Xb = X + ((size_t)b * Ss + s0) * Hh;

    // ---- W cp.async mapping: 4 ops per thread (2048 x 16B per stage)
    const __nv_bfloat16* wsrc[4];
    uint32_t wdst[4];
#pragma unroll
    for (int i = 0; i < 4; i++) {
        int l = tid * 4 + i;
        int pl = l >> 10, row = (l & 1023) >> 2, ch = l & 3;
        wsrc[i] = (pl ? g_Wlo : g_Whi) + ((size_t)(ah * 256 + row)) * Hh + ch * 8;
        wdst[i] = OFF_WHI + pl * 20480 + row * 80 + ch * 16;
    }

    auto issueW = [&](int ck, int slot) {
        uint32_t sb = sbase + (uint32_t)slot * STG_SZ;
        int ko = ck * 32;
#pragma unroll
        for (int i = 0; i < 4; i++) cp_async16(sb + wdst[i], wsrc[i] + ko);
    };
    auto loadX = [&](int ck, float4& v0, float4& v1) {
        v0 = *(const float4*)(Xb + (size_t)xrow0 * Hh + ck * 32 + xq0 * 4);
        v1 = *(const float4*)(Xb + (size_t)xrow1 * Hh + ck * 32 + xq1 * 4);
    };
    auto storeX = [&](int slot, float4 v0, float4 v1) {
        char* sp = smem + slot * STG_SZ;
        union U { __nv_bfloat16 h[4]; uint2 u; };
        float f0[4] = {v0.x, v0.y, v0.z, v0.w};
        float f1[4] = {v1.x, v1.y, v1.z, v1.w};
        U h0, l0, h1, l1;
#pragma unroll
        for (int e = 0; e < 4; e++) {
            h0.h[e] = __float2bfloat16(f0[e]);
            l0.h[e] = __float2bfloat16(f0[e] - __bfloat162float(h0.h[e]));
            h1.h[e] = __float2bfloat16(f1[e]);
            l1.h[e] = __float2bfloat16(f1[e] - __bfloat162float(h1.h[e]));
        }
        *(uint2*)(sp + xrow0 * 80 + xq0 * 8) = h0.u;
        *(uint2*)(sp + OFF_XLO + xrow0 * 80 + xq0 * 8) = l0.u;
        *(uint2*)(sp + xrow1 * 80 + xq1 * 8) = h1.u;
        *(uint2*)(sp + OFF_XLO + xrow1 * 80 + xq1 * 8) = l1.u;
    };

    // ---- ldmatrix lane geometry (80B rows)
    uint32_t t8 = lane >> 3;
    uint32_t l7 = lane & 7;
    uint32_t arow[2], nrow[4];
#pragma unroll
    for (int i = 0; i < 2; i++)
        arow[i] = (wm * 32 + i * 16 + ((t8 & 1) << 3) + l7) * 80;
#pragma unroll
    for (int g = 0; g < 4; g++)
        nrow[g] = (wn * 64 + (g * 2 + (t8 >> 1)) * 8 + l7) * 80;
    uint32_t ka = (t8 >> 1) << 4;
    uint32_t kb_b = (t8 & 1) << 4;

    float acc[2][8][4];
#pragma unroll
    for (int i = 0; i < 2; i++)
#pragma unroll
        for (int j = 0; j < 8; j++)
#pragma unroll
            for (int r = 0; r < 4; r++) acc[i][j][r] = 0.f;

    // ---- prologue: X for stages 0,1 stored; W for 0,1 issued; X(2) in regs
    float4 pv0, pv1;
    loadX(0, pv0, pv1);
    storeX(0, pv0, pv1);
    issueW(0, 0); cp_commit();
    loadX(1, pv0, pv1);
    storeX(1, pv0, pv1);
    issueW(1, 1); cp_commit();
    loadX(2, pv0, pv1);

    // ---- main loop: one barrier per k-chunk
#pragma unroll 1
    for (int ck = 0; ck < 32; ck++) {
        asm volatile("cp.async.wait_group 1;" ::: "memory");
        __syncthreads();   // all warps done with slot (ck-1)%3; stage ck X/W visible

        int fs = ck + 2;
        if (fs < 32) {
            int ns = fs - (fs / 3) * 3;       // (ck+2)%3 == slot of ck-1, now free
            storeX(ns, pv0, pv1);
            issueW(fs, ns);
        }
        cp_commit();
        if (ck + 3 < 32) loadX(ck + 3, pv0, pv1);

        uint32_t sb = sbase + (uint32_t)(ck - (ck / 3) * 3) * STG_SZ;
#pragma unroll
        for (int sp = 0; sp < 3; sp++) {
            uint32_t Ab = sb + (sp == 2 ? OFF_XLO : 0u);
            uint32_t Bbs = sb + (sp == 1 ? OFF_WLO : OFF_WHI);
#pragma unroll
            for (int kf = 0; kf < 2; kf++) {
                uint32_t k16 = kf * 32;
                uint32_t a[2][4];
#pragma unroll
                for (int i = 0; i < 2; i++)
                    ldmx4(a[i][0], a[i][1], a[i][2], a[i][3], Ab + arow[i] + k16 + ka);
                uint32_t bf[8][2];
#pragma unroll
                for (int g = 0; g < 4; g++) {
                    uint32_t r0, r1, r2, r3;
                    ldmx4(r0, r1, r2, r3, Bbs + nrow[g] + k16 + kb_b);
                    bf[2 * g][0] = r0; bf[2 * g][1] = r1;
                    bf[2 * g + 1][0] = r2; bf[2 * g + 1][1] = r3;
                }
#pragma unroll
                for (int i = 0; i < 2; i++)
#pragma unroll
                    for (int j = 0; j < 8; j++)
                        mma_bf16(acc[i][j], a[i], bf[j]);
            }
        }
    }

    // ---- epilogue: relu(acc + C) dot V, reduce to per-row scores
    float rs[4] = {0.f, 0.f, 0.f, 0.f};
#pragma unroll
    for (int i = 0; i < 2; i++) {
#pragma unroll
        for (int j = 0; j < 8; j++) {
            int c = wn * 64 + j * 8 + (lane & 3) * 2;
            float v0 = vs[c], v1 = vs[c + 1];
            float c0 = cs[c], c1 = cs[c + 1];
            rs[i * 2 + 0] += fmaxf(acc[i][j][0] + c0, 0.f) * v0
                           + fmaxf(acc[i][j][1] + c1, 0.f) * v1;
            rs[i * 2 + 1] += fmaxf(acc[i][j][2] + c0, 0.f) * v0
                           + fmaxf(acc[i][j][3] + c1, 0.f) * v1;
        }
    }
#pragma unroll
    for (int r = 0; r < 4; r++) {
        rs[r] += __shfl_xor_sync(0xffffffffu, rs[r], 1);
        rs[r] += __shfl_xor_sync(0xffffffffu, rs[r], 2);
    }
    float* scp = (float*)(smem + OFF_SCP);
    __syncthreads();
    if ((lane & 3) == 0) {
        int row = wm * 32 + (lane >> 2);
        scp[wn * 128 + row + 0]  = rs[0];
        scp[wn * 128 + row + 8]  = rs[1];
        scp[wn * 128 + row + 16] = rs[2];
        scp[wn * 128 + row + 24] = rs[3];
    }
    __syncthreads();
    if (tid < 128) {
        float v = scp[tid] + scp[128 + tid] + scp[256 + tid] + scp[384 + tid];
        (ah ? g_sc1 : g_sc0)[b * Ss + s0 + tid] = v;
    }
}

// ---------------------------------------------------------------------------
// softmax over s<len of (g_sc0+g_sc1); prob -> out[B*H ...]
// ---------------------------------------------------------------------------
__global__ void softmax_kernel(const int* __restrict__ lengths, float* __restrict__ out) {
    int b = blockIdx.x;
    int len = lengths[b];
    int tid = threadIdx.x;
    const float* a0 = g_sc0 + b * Ss;
    const float* a1 = g_sc1 + b * Ss;
    float* prob = out + Bb * Hh + (size_t)b * Ss;

    __shared__ float red[8];
    __shared__ float s_m, s_sum;

    float m = -CUDART_INF_F;
    for (int s = tid; s < len; s += 256) m = fmaxf(m, a0[s] + a1[s]);
#pragma unroll
    for (int o = 16; o > 0; o >>= 1) m = fmaxf(m, __shfl_xor_sync(~0u, m, o));
    if ((tid & 31) == 0) red[tid >> 5] = m;
    __syncthreads();
    if (tid == 0) {
        float mm = red[0];
#pragma unroll
        for (int i = 1; i < 8; i++) mm = fmaxf(mm, red[i]);
        s_m = mm;
    }
    __syncthreads();
    m = s_m;

    float sum = 0.f;
    for (int s = tid; s < len; s += 256) sum += expf(a0[s] + a1[s] - m);
#pragma unroll
    for (int o = 16; o > 0; o >>= 1) sum += __shfl_xor_sync(~0u, sum, o);
    if ((tid & 31) == 0) red[tid >> 5] = sum;
    __syncthreads();
    if (tid == 0) {
        float ss = 0.f;
#pragma unroll
        for (int i = 0; i < 8; i++) ss += red[i];
        s_sum = ss;
    }
    __syncthreads();
    float inv = 1.f / s_sum;

    for (int s = tid; s < Ss; s += 256)
        prob[s] = (s < len) ? expf(a0[s] + a1[s] - m) * inv : 0.f;
}

// ---------------------------------------------------------------------------
// output pass, two-phase
// ---------------------------------------------------------------------------
__global__ void output_partial(const float* __restrict__ X,
                               const int* __restrict__ lengths,
                               const float* __restrict__ out) {
    int sc = blockIdx.x, b = blockIdx.y;
    int len = lengths[b];
    int s0 = sc * 128;
    if (s0 >= len) return;
    int n = min(128, len - s0);
    int tid = threadIdx.x;
    const float4* Xb = (const float4*)X + ((size_t)(b * Ss + s0)) * 256 + tid;
    const float* prob = out + Bb * Hh + (size_t)b * Ss + s0;
    float4 acc = make_float4(0.f, 0.f, 0.f, 0.f);
#pragma unroll 4
    for (int s = 0; s < n; s++) {
        float p = __ldg(prob + s);
        float4 x = Xb[(size_t)s * 256];
        acc.x = fmaf(p, x.x, acc.x);
        acc.y = fmaf(p, x.y, acc.y);
        acc.z = fmaf(p, x.z, acc.z);
        acc.w = fmaf(p, x.w, acc.w);
    }
    ((float4*)g_opart)[(b * 16 + sc) * 256 + tid] = acc;
}

__global__ void output_reduce(const int* __restrict__ lengths, float* __restrict__ out) {
    int b = blockIdx.x;
    int tid = threadIdx.x;
    int kmax = min(16, (lengths[b] + 127) >> 7);
    float4 acc = make_float4(0.f, 0.f, 0.f, 0.f);
    for (int c = 0; c < kmax; c++) {
        float4 v = ((const float4*)g_opart)[(b * 16 + c) * 256 + tid];
        acc.x += v.x; acc.y += v.y; acc.z += v.z; acc.w += v.w;
    }
    ((float4*)out)[b * 256 + tid] = acc;
}

// ---------------------------------------------------------------------------
extern "C" void kernel_launch(void* const* d_in, const int* in_sizes, int n_in,
                              void* d_out, int out_size) {
    const float* X   = (const float*)d_in[0];
    const float* x0  = (const float*)d_in[1];
    const float* x1  = (const float*)d_in[2];
    const float* x2  = (const float*)d_in[3];
    const int*   len = (const int*)  d_in[4];
    const float* WhW = (const float*)d_in[5];
    const float* WhB = (const float*)d_in[6];
    const float* W0  = (const float*)d_in[7];
    const float* W1  = (const float*)d_in[8];
    const float* W2  = (const float*)d_in[9];
    const float* V   = (const float*)d_in[10];
    float* out = (float*)d_out;

    static bool attr_done = false;
    if (!attr_done) {
        cudaFuncSetAttribute(scores_mma, cudaFuncAttributeMaxDynamicSharedMemorySize, SMEM_SZ);
        attr_done = true;
    }

    prep_w<<<512, 256>>>(WhW);
    ctx_kernel<<<Bb, 512>>>(x0, x1, x2, W0, W1, W2, WhB);
    scores_mma<<<dim3(16, 2, Bb), 512, SMEM_SZ>>>(X, V, len);
    softmax_kernel<<<Bb, 256>>>(len, out);
    output_partial<<<dim3(16, Bb), 256>>>(X, len, out);
    output_reduce<<<Bb, 256>>>(len, out);
}

// round 7
// speedup vs baseline: 1.8614x; 1.8614x over previous
#include <cuda_runtime.h>
#include <cuda_fp16.h>
#include <math_constants.h>
#include <cstdint>

#define Bb 64
#define Ss 2048
#define Hh 1024
#define Aa 512

// ---------------- device scratch (no allocation allowed) --------------------
__device__ float g_C[Bb * Aa];
__device__ float g_sc0[Bb * Ss];
__device__ float g_sc1[Bb * Ss];
__device__ float g_opart[Bb * 16 * Hh];
__device__ __half g_W16[Aa * Hh];

// ---------------- helpers ---------------------------------------------------
__device__ __forceinline__ uint32_t smem_u32(const void* p) {
    uint32_t a;
    asm("{ .reg .u64 t; cvta.to.shared.u64 t, %1; cvt.u32.u64 %0, t; }" : "=r"(a) : "l"(p));
    return a;
}
__device__ __forceinline__ void cp_async16(uint32_t dst, const void* src) {
    asm volatile("cp.async.cg.shared.global [%0], [%1], 16;" :: "r"(dst), "l"(src) : "memory");
}
__device__ __forceinline__ void cp_commit() {
    asm volatile("cp.async.commit_group;" ::: "memory");
}
__device__ __forceinline__ void ldmx4(uint32_t& r0, uint32_t& r1, uint32_t& r2, uint32_t& r3,
                                      uint32_t addr) {
    asm volatile("ldmatrix.sync.aligned.m8n8.x4.shared.b16 {%0,%1,%2,%3}, [%4];"
                 : "=r"(r0), "=r"(r1), "=r"(r2), "=r"(r3) : "r"(addr));
}
__device__ __forceinline__ void mma_f16(float* d, const uint32_t* a, const uint32_t* b) {
    asm volatile(
        "mma.sync.aligned.m16n8k16.row.col.f32.f16.f16.f32 "
        "{%0,%1,%2,%3}, {%4,%5,%6,%7}, {%8,%9}, {%0,%1,%2,%3};"
        : "+f"(d[0]), "+f"(d[1]), "+f"(d[2]), "+f"(d[3])
        : "r"(a[0]), "r"(a[1]), "r"(a[2]), "r"(a[3]), "r"(b[0]), "r"(b[1]));
}

// smem: 2 stages of [X16 10240 | Xr 10240 | W16 20480]  (80B rows)
#define STG_SZ   40960
#define OFF_XR   10240
#define OFF_W    20480
#define OFF_SCP  81920            // 512 floats
#define OFF_CS   83968            // 256 floats
#define OFF_VS   84992            // 256 floats
#define SMEM_SZ  86016

// ---------------------------------------------------------------------------
// prep_w: round Wh (fp32 [512][1024]) to fp16, row-major single plane.
// ---------------------------------------------------------------------------
__global__ void prep_w(const float* __restrict__ Wh) {
    int a = blockIdx.x;
    int t = threadIdx.x;
    float4 v = *(const float4*)(Wh + (size_t)a * 1024 + t * 4);
    union U { __half h[4]; uint2 u; };
    U w;
    w.h[0] = __float2half_rn(v.x);
    w.h[1] = __float2half_rn(v.y);
    w.h[2] = __float2half_rn(v.z);
    w.h[3] = __float2half_rn(v.w);
    *(uint2*)(g_W16 + (size_t)a * 1024 + t * 4) = w.u;
}

// ---------------------------------------------------------------------------
// ctx: C[b,a] = Wh_b[a] + x0@W0[a] + x1@W1[a] + x2@W2[a]
// ---------------------------------------------------------------------------
__global__ void ctx_kernel(const float* __restrict__ x0,
                           const float* __restrict__ x1,
                           const float* __restrict__ x2,
                           const float* __restrict__ W0,
                           const float* __restrict__ W1,
                           const float* __restrict__ W2,
                           const float* __restrict__ Whb) {
    __shared__ float xs[2048];
    int b = blockIdx.x;
    int t = threadIdx.x;
    xs[t]        = x0[b * 1024 + t];
    xs[t + 512]  = x0[b * 1024 + t + 512];
    xs[1024 + t] = x1[b * 512 + t];
    xs[1536 + t] = x2[b * 512 + t];
    __syncthreads();
    int a = t;
    float acc = Whb[a];
    const float4* w0 = (const float4*)(W0 + (size_t)a * 1024);
    const float4* xv = (const float4*)xs;
#pragma unroll 8
    for (int i = 0; i < 256; i++) {
        float4 w = w0[i]; float4 x = xv[i];
        acc += w.x * x.x + w.y * x.y + w.z * x.z + w.w * x.w;
    }
    const float4* w1 = (const float4*)(W1 + (size_t)a * 512);
    const float4* x1v = (const float4*)(xs + 1024);
#pragma unroll 8
    for (int i = 0; i < 128; i++) {
        float4 w = w1[i]; float4 x = x1v[i];
        acc += w.x * x.x + w.y * x.y + w.z * x.z + w.w * x.w;
    }
    const float4* w2 = (const float4*)(W2 + (size_t)a * 512);
    const float4* x2v = (const float4*)(xs + 1536);
#pragma unroll 8
    for (int i = 0; i < 128; i++) {
        float4 w = w2[i]; float4 x = x2v[i];
        acc += w.x * x.x + w.y * x.y + w.z * x.z + w.w * x.w;
    }
    g_C[b * Aa + a] = acc;
}

// ---------------------------------------------------------------------------
// scores_mma: fused scores. fp16 two-term: Ah = x16@W16^T + r16@W16^T,
// where x16=fp16(x), r16=fp16(x-x16), W16=fp16(W). B fragments shared by
// both A planes. Round-3 skeleton: 2 stages, 2 barriers per k-chunk.
// grid (16 st, 2 ah, 64 b), 512 threads (16 warps 4x4), warp 32x64, BK=32.
// ---------------------------------------------------------------------------
__global__ void __launch_bounds__(512)
scores_mma(const float* __restrict__ X,
           const float* __restrict__ V,
           const int* __restrict__ lengths) {
    extern __shared__ char smem[];
    int st = blockIdx.x, ah = blockIdx.y, b = blockIdx.z;
    int len = lengths[b];
    int s0 = st * 128;
    if (s0 >= len) return;

    int tid = threadIdx.x;
    int wid = tid >> 5;
    int lane = tid & 31;
    int wm = wid >> 2;
    int wn = wid & 3;

    float* cs = (float*)(smem + OFF_CS);
    float* vs = (float*)(smem + OFF_VS);
    if (tid < 256) {
        cs[tid] = g_C[b * Aa + ah * 256 + tid];
        vs[tid] = V[ah * 256 + tid];
    }

    uint32_t sbase = smem_u32(smem);

    // ---- X mapping: 2 float4 per thread (128 rows x 32 fp32 cols per stage)
    int xrow0 = (tid * 2) >> 3;
    int xq0   = (tid * 2) & 7;
    int xrow1 = (tid * 2 + 1) >> 3;
    int xq1   = (tid * 2 + 1) & 7;
    const float* Xb = X + ((size_t)b * Ss + s0) * Hh;

    // ---- W cp.async mapping: 2 ops per thread (256 rows x 4 chunks of 16B)
    const __half* wsrc[2];
    uint32_t wdst[2];
#pragma unroll
    for (int i = 0; i < 2; i++) {
        int l = tid * 2 + i;
        int row = l >> 2, ch = l & 3;
        wsrc[i] = g_W16 + ((size_t)(ah * 256 + row)) * Hh + ch * 8;
        wdst[i] = OFF_W + row * 80 + ch * 16;
    }

    auto issueW = [&](int ck, uint32_t stage_u32) {
        int ko = ck * 32;
#pragma unroll
        for (int i = 0; i < 2; i++) cp_async16(stage_u32 + wdst[i], wsrc[i] + ko);
        cp_commit();
    };
    auto loadX = [&](int ck, float4& v0, float4& v1) {
        v0 = *(const float4*)(Xb + (size_t)xrow0 * Hh + ck * 32 + xq0 * 4);
        v1 = *(const float4*)(Xb + (size_t)xrow1 * Hh + ck * 32 + xq1 * 4);
    };
    auto storeX = [&](char* sp, float4 v0, float4 v1) {
        union U { __half h[4]; uint2 u; };
        float f0[4] = {v0.x, v0.y, v0.z, v0.w};
        float f1[4] = {v1.x, v1.y, v1.z, v1.w};
        U h0, r0, h1, r1;
#pragma unroll
        for (int e = 0; e < 4; e++) {
            h0.h[e] = __float2half_rn(f0[e]);
            r0.h[e] = __float2half_rn(f0[e] - __half2float(h0.h[e]));
            h1.h[e] = __float2half_rn(f1[e]);
            r1.h[e] = __float2half_rn(f1[e] - __half2float(h1.h[e]));
        }
        *(uint2*)(sp + xrow0 * 80 + xq0 * 8) = h0.u;
        *(uint2*)(sp + OFF_XR + xrow0 * 80 + xq0 * 8) = r0.u;
        *(uint2*)(sp + xrow1 * 80 + xq1 * 8) = h1.u;
        *(uint2*)(sp + OFF_XR + xrow1 * 80 + xq1 * 8) = r1.u;
    };

    // ---- ldmatrix lane geometry (80B rows)
    uint32_t t8 = lane >> 3;
    uint32_t l7 = lane & 7;
    uint32_t arow[2], nrow[4];
#pragma unroll
    for (int i = 0; i < 2; i++)
        arow[i] = (wm * 32 + i * 16 + ((t8 & 1) << 3) + l7) * 80;
#pragma unroll
    for (int g = 0; g < 4; g++)
        nrow[g] = (wn * 64 + (g * 2 + (t8 >> 1)) * 8 + l7) * 80;
    uint32_t ka = (t8 >> 1) << 4;
    uint32_t kb_b = (t8 & 1) << 4;

    float acc[2][8][4];
#pragma unroll
    for (int i = 0; i < 2; i++)
#pragma unroll
        for (int j = 0; j < 8; j++)
#pragma unroll
            for (int r = 0; r < 4; r++) acc[i][j][r] = 0.f;

    // ---- prologue: fill stages 0,1
    {
        float4 v0, v1;
        issueW(0, sbase);
        loadX(0, v0, v1);
        storeX(smem, v0, v1);
        issueW(1, sbase + STG_SZ);
        loadX(1, v0, v1);
        storeX(smem + STG_SZ, v0, v1);
    }

    // ---- main loop (round-3 skeleton: 2 barriers per k-chunk)
    float4 pv0, pv1;
#pragma unroll 1
    for (int ck = 0; ck < 32; ck++) {
        if (ck == 31) asm volatile("cp.async.wait_group 0;" ::: "memory");
        else          asm volatile("cp.async.wait_group 1;" ::: "memory");
        __syncthreads();

        if (ck + 2 <= 31) loadX(ck + 2, pv0, pv1);

        uint32_t sb = sbase + (uint32_t)(ck & 1) * STG_SZ;
#pragma unroll
        for (int kf = 0; kf < 2; kf++) {
            uint32_t k16 = kf * 32;
            // B fragments once, reused by both A planes
            uint32_t bf[8][2];
#pragma unroll
            for (int g = 0; g < 4; g++) {
                uint32_t r0, r1, r2, r3;
                ldmx4(r0, r1, r2, r3, sb + OFF_W + nrow[g] + k16 + kb_b);
                bf[2 * g][0] = r0; bf[2 * g][1] = r1;
                bf[2 * g + 1][0] = r2; bf[2 * g + 1][1] = r3;
            }
            uint32_t a16[2][4], ar[2][4];
#pragma unroll
            for (int i = 0; i < 2; i++) {
                ldmx4(a16[i][0], a16[i][1], a16[i][2], a16[i][3], sb + arow[i] + k16 + ka);
                ldmx4(ar[i][0], ar[i][1], ar[i][2], ar[i][3], sb + OFF_XR + arow[i] + k16 + ka);
            }
#pragma unroll
            for (int i = 0; i < 2; i++)
#pragma unroll
                for (int j = 0; j < 8; j++)
                    mma_f16(acc[i][j], a16[i], bf[j]);
#pragma unroll
            for (int i = 0; i < 2; i++)
#pragma unroll
                for (int j = 0; j < 8; j++)
                    mma_f16(acc[i][j], ar[i], bf[j]);
        }
        __syncthreads();

        if (ck + 2 <= 31) {
            storeX(smem + (ck & 1) * STG_SZ, pv0, pv1);
            issueW(ck + 2, sbase + (uint32_t)(ck & 1) * STG_SZ);
        }
    }

    // ---- epilogue: relu(acc + C) dot V, reduce to per-row scores
    float rs[4] = {0.f, 0.f, 0.f, 0.f};
#pragma unroll
    for (int i = 0; i < 2; i++) {
#pragma unroll
        for (int j = 0; j < 8; j++) {
            int c = wn * 64 + j * 8 + (lane & 3) * 2;
            float v0 = vs[c], v1 = vs[c + 1];
            float c0 = cs[c], c1 = cs[c + 1];
            rs[i * 2 + 0] += fmaxf(acc[i][j][0] + c0, 0.f) * v0
                           + fmaxf(acc[i][j][1] + c1, 0.f) * v1;
            rs[i * 2 + 1] += fmaxf(acc[i][j][2] + c0, 0.f) * v0
                           + fmaxf(acc[i][j][3] + c1, 0.f) * v1;
        }
    }
#pragma unroll
    for (int r = 0; r < 4; r++) {
        rs[r] += __shfl_xor_sync(0xffffffffu, rs[r], 1);
        rs[r] += __shfl_xor_sync(0xffffffffu, rs[r], 2);
    }
    float* scp = (float*)(smem + OFF_SCP);
    if ((lane & 3) == 0) {
        int row = wm * 32 + (lane >> 2);
        scp[wn * 128 + row + 0]  = rs[0];
        scp[wn * 128 + row + 8]  = rs[1];
        scp[wn * 128 + row + 16] = rs[2];
        scp[wn * 128 + row + 24] = rs[3];
    }
    __syncthreads();
    if (tid < 128) {
        float v = scp[tid] + scp[128 + tid] + scp[256 + tid] + scp[384 + tid];
        (ah ? g_sc1 : g_sc0)[b * Ss + s0 + tid] = v;
    }
}

// ---------------------------------------------------------------------------
// softmax over s<len of (g_sc0+g_sc1); prob -> out[B*H ...]
// ---------------------------------------------------------------------------
__global__ void softmax_kernel(const int* __restrict__ lengths, float* __restrict__ out) {
    int b = blockIdx.x;
    int len = lengths[b];
    int tid = threadIdx.x;
    const float* a0 = g_sc0 + b * Ss;
    const float* a1 = g_sc1 + b * Ss;
    float* prob = out + Bb * Hh + (size_t)b * Ss;

    __shared__ float red[8];
    __shared__ float s_m, s_sum;

    float m = -CUDART_INF_F;
    for (int s = tid; s < len; s += 256) m = fmaxf(m, a0[s] + a1[s]);
#pragma unroll
    for (int o = 16; o > 0; o >>= 1) m = fmaxf(m, __shfl_xor_sync(~0u, m, o));
    if ((tid & 31) == 0) red[tid >> 5] = m;
    __syncthreads();
    if (tid == 0) {
        float mm = red[0];
#pragma unroll
        for (int i = 1; i < 8; i++) mm = fmaxf(mm, red[i]);
        s_m = mm;
    }
    __syncthreads();
    m = s_m;

    float sum = 0.f;
    for (int s = tid; s < len; s += 256) sum += expf(a0[s] + a1[s] - m);
#pragma unroll
    for (int o = 16; o > 0; o >>= 1) sum += __shfl_xor_sync(~0u, sum, o);
    if ((tid & 31) == 0) red[tid >> 5] = sum;
    __syncthreads();
    if (tid == 0) {
        float ss = 0.f;
#pragma unroll
        for (int i = 0; i < 8; i++) ss += red[i];
        s_sum = ss;
    }
    __syncthreads();
    float inv = 1.f / s_sum;

    for (int s = tid; s < Ss; s += 256)
        prob[s] = (s < len) ? expf(a0[s] + a1[s] - m) * inv : 0.f;
}

// ---------------------------------------------------------------------------
// output pass, two-phase
// ---------------------------------------------------------------------------
__global__ void output_partial(const float* __restrict__ X,
                               const int* __restrict__ lengths,
                               const float* __restrict__ out) {
    int sc = blockIdx.x, b = blockIdx.y;
    int len = lengths[b];
    int s0 = sc * 128;
    if (s0 >= len) return;
    int n = min(128, len - s0);
    int tid = threadIdx.x;
    const float4* Xb = (const float4*)X + ((size_t)(b * Ss + s0)) * 256 + tid;
    const float* prob = out + Bb * Hh + (size_t)b * Ss + s0;
    float4 acc = make_float4(0.f, 0.f, 0.f, 0.f);
#pragma unroll 4
    for (int s = 0; s < n; s++) {
        float p = __ldg(prob + s);
        float4 x = Xb[(size_t)s * 256];
        acc.x = fmaf(p, x.x, acc.x);
        acc.y = fmaf(p, x.y, acc.y);
        acc.z = fmaf(p, x.z, acc.z);
        acc.w = fmaf(p, x.w, acc.w);
    }
    ((float4*)g_opart)[(b * 16 + sc) * 256 + tid] = acc;
}

__global__ void output_reduce(const int* __restrict__ lengths, float* __restrict__ out) {
    int b = blockIdx.x;
    int tid = threadIdx.x;
    int kmax = min(16, (lengths[b] + 127) >> 7);
    float4 acc = make_float4(0.f, 0.f, 0.f, 0.f);
    for (int c = 0; c < kmax; c++) {
        float4 v = ((const float4*)g_opart)[(b * 16 + c) * 256 + tid];
        acc.x += v.x; acc.y += v.y; acc.z += v.z; acc.w += v.w;
    }
    ((float4*)out)[b * 256 + tid] = acc;
}

// ---------------------------------------------------------------------------
extern "C" void kernel_launch(void* const* d_in, const int* in_sizes, int n_in,
                              void* d_out, int out_size) {
    const float* X   = (const float*)d_in[0];
    const float* x0  = (const float*)d_in[1];
    const float* x1  = (const float*)d_in[2];
    const float* x2  = (const float*)d_in[3];
    const int*   len = (const int*)  d_in[4];
    const float* WhW = (const float*)d_in[5];
    const float* WhB = (const float*)d_in[6];
    const float* W0  = (const float*)d_in[7];
    const float* W1  = (const float*)d_in[8];
    const float* W2  = (const float*)d_in[9];
    const float* V   = (const float*)d_in[10];
    float* out = (float*)d_out;

    static bool attr_done = false;
    if (!attr_done) {
        cudaFuncSetAttribute(scores_mma, cudaFuncAttributeMaxDynamicSharedMemorySize, SMEM_SZ);
        attr_done = true;
    }

    prep_w<<<512, 256>>>(WhW);
    ctx_kernel<<<Bb, 512>>>(x0, x1, x2, W0, W1, W2, WhB);
    scores_mma<<<dim3(16, 2, Bb), 512, SMEM_SZ>>>(X, V, len);
    softmax_kernel<<<Bb, 256>>>(len, out);
    output_partial<<<dim3(16, Bb), 256>>>(X, len, out);
    output_reduce<<<Bb, 256>>>(len, out);
}

// round 8
// speedup vs baseline: 2.4212x; 1.3007x over previous
#include <cuda_runtime.h>
#include <cuda_fp16.h>
#include <math_constants.h>
#include <cstdint>

#define Bb 64
#define Ss 2048
#define Hh 1024
#define Aa 512

// ---------------- device scratch (no allocation allowed) --------------------
__device__ float g_C[Bb * Aa];
__device__ float g_sc0[Bb * Ss];
__device__ float g_sc1[Bb * Ss];
__device__ float g_opart[Bb * 16 * Hh];
__device__ __half g_W16[Aa * Hh];

// ---------------- helpers ---------------------------------------------------
__device__ __forceinline__ uint32_t smem_u32(const void* p) {
    uint32_t a;
    asm("{ .reg .u64 t; cvta.to.shared.u64 t, %1; cvt.u32.u64 %0, t; }" : "=r"(a) : "l"(p));
    return a;
}
__device__ __forceinline__ void cp_async16(uint32_t dst, const void* src) {
    asm volatile("cp.async.cg.shared.global [%0], [%1], 16;" :: "r"(dst), "l"(src) : "memory");
}
__device__ __forceinline__ void cp_commit() {
    asm volatile("cp.async.commit_group;" ::: "memory");
}
__device__ __forceinline__ void ldmx4(uint32_t& r0, uint32_t& r1, uint32_t& r2, uint32_t& r3,
                                      uint32_t addr) {
    asm volatile("ldmatrix.sync.aligned.m8n8.x4.shared.b16 {%0,%1,%2,%3}, [%4];"
                 : "=r"(r0), "=r"(r1), "=r"(r2), "=r"(r3) : "r"(addr));
}
__device__ __forceinline__ void mma_f16(float* d, const uint32_t* a, const uint32_t* b) {
    asm volatile(
        "mma.sync.aligned.m16n8k16.row.col.f32.f16.f16.f32 "
        "{%0,%1,%2,%3}, {%4,%5,%6,%7}, {%8,%9}, {%0,%1,%2,%3};"
        : "+f"(d[0]), "+f"(d[1]), "+f"(d[2]), "+f"(d[3])
        : "r"(a[0]), "r"(a[1]), "r"(a[2]), "r"(a[3]), "r"(b[0]), "r"(b[1]));
}

// smem: 2 stages of [X16 10240 | W16 20480]  (80B rows)
#define STG_SZ   30720
#define OFF_W    10240
#define OFF_SCP  61440            // 512 floats
#define OFF_CS   63488            // 256 floats
#define OFF_VS   64512            // 256 floats
#define SMEM_SZ  65536

// ---------------------------------------------------------------------------
// prep_w: round Wh (fp32 [512][1024]) to fp16, row-major single plane.
// ---------------------------------------------------------------------------
__global__ void prep_w(const float* __restrict__ Wh) {
    int a = blockIdx.x;
    int t = threadIdx.x;
    float4 v = *(const float4*)(Wh + (size_t)a * 1024 + t * 4);
    union U { __half h[4]; uint2 u; };
    U w;
    w.h[0] = __float2half_rn(v.x);
    w.h[1] = __float2half_rn(v.y);
    w.h[2] = __float2half_rn(v.z);
    w.h[3] = __float2half_rn(v.w);
    *(uint2*)(g_W16 + (size_t)a * 1024 + t * 4) = w.u;
}

// ---------------------------------------------------------------------------
// ctx: C[b,a] = Wh_b[a] + x0@W0[a] + x1@W1[a] + x2@W2[a]
// ---------------------------------------------------------------------------
__global__ void ctx_kernel(const float* __restrict__ x0,
                           const float* __restrict__ x1,
                           const float* __restrict__ x2,
                           const float* __restrict__ W0,
                           const float* __restrict__ W1,
                           const float* __restrict__ W2,
                           const float* __restrict__ Whb) {
    __shared__ float xs[2048];
    int b = blockIdx.x;
    int t = threadIdx.x;
    xs[t]        = x0[b * 1024 + t];
    xs[t + 512]  = x0[b * 1024 + t + 512];
    xs[1024 + t] = x1[b * 512 + t];
    xs[1536 + t] = x2[b * 512 + t];
    __syncthreads();
    int a = t;
    float acc = Whb[a];
    const float4* w0 = (const float4*)(W0 + (size_t)a * 1024);
    const float4* xv = (const float4*)xs;
#pragma unroll 8
    for (int i = 0; i < 256; i++) {
        float4 w = w0[i]; float4 x = xv[i];
        acc += w.x * x.x + w.y * x.y + w.z * x.z + w.w * x.w;
    }
    const float4* w1 = (const float4*)(W1 + (size_t)a * 512);
    const float4* x1v = (const float4*)(xs + 1024);
#pragma unroll 8
    for (int i = 0; i < 128; i++) {
        float4 w = w1[i]; float4 x = x1v[i];
        acc += w.x * x.x + w.y * x.y + w.z * x.z + w.w * x.w;
    }
    const float4* w2 = (const float4*)(W2 + (size_t)a * 512);
    const float4* x2v = (const float4*)(xs + 1536);
#pragma unroll 8
    for (int i = 0; i < 128; i++) {
        float4 w = w2[i]; float4 x = x2v[i];
        acc += w.x * x.x + w.y * x.y + w.z * x.z + w.w * x.w;
    }
    g_C[b * Aa + a] = acc;
}

// ---------------------------------------------------------------------------
// scores_mma: fused scores, single-pass fp16: Ah ~= fp16(x) @ fp16(W)^T.
// Round-3 skeleton: 2 stages, 2 barriers per k-chunk.
// grid (16 st, 2 ah, 64 b), 512 threads (16 warps 4x4), warp 32x64, BK=32.
// ---------------------------------------------------------------------------
__global__ void __launch_bounds__(512)
scores_mma(const float* __restrict__ X,
           const float* __restrict__ V,
           const int* __restrict__ lengths) {
    extern __shared__ char smem[];
    int st = blockIdx.x, ah = blockIdx.y, b = blockIdx.z;
    int len = lengths[b];
    int s0 = st * 128;
    if (s0 >= len) return;

    int tid = threadIdx.x;
    int wid = tid >> 5;
    int lane = tid & 31;
    int wm = wid >> 2;
    int wn = wid & 3;

    float* cs = (float*)(smem + OFF_CS);
    float* vs = (float*)(smem + OFF_VS);
    if (tid < 256) {
        cs[tid] = g_C[b * Aa + ah * 256 + tid];
        vs[tid] = V[ah * 256 + tid];
    }

    uint32_t sbase = smem_u32(smem);

    // ---- X mapping: 2 float4 per thread (128 rows x 32 fp32 cols per stage)
    int xrow0 = (tid * 2) >> 3;
    int xq0   = (tid * 2) & 7;
    int xrow1 = (tid * 2 + 1) >> 3;
    int xq1   = (tid * 2 + 1) & 7;
    const float* Xb = X + ((size_t)b * Ss + s0) * Hh;

    // ---- W cp.async mapping: 2 ops per thread (256 rows x 4 chunks of 16B)
    const __half* wsrc[2];
    uint32_t wdst[2];
#pragma unroll
    for (int i = 0; i < 2; i++) {
        int l = tid * 2 + i;
        int row = l >> 2, ch = l & 3;
        wsrc[i] = g_W16 + ((size_t)(ah * 256 + row)) * Hh + ch * 8;
        wdst[i] = OFF_W + row * 80 + ch * 16;
    }

    auto issueW = [&](int ck, uint32_t stage_u32) {
        int ko = ck * 32;
#pragma unroll
        for (int i = 0; i < 2; i++) cp_async16(stage_u32 + wdst[i], wsrc[i] + ko);
        cp_commit();
    };
    auto loadX = [&](int ck, float4& v0, float4& v1) {
        v0 = *(const float4*)(Xb + (size_t)xrow0 * Hh + ck * 32 + xq0 * 4);
        v1 = *(const float4*)(Xb + (size_t)xrow1 * Hh + ck * 32 + xq1 * 4);
    };
    auto storeX = [&](char* sp, float4 v0, float4 v1) {
        union U { __half h[4]; uint2 u; };
        U h0, h1;
        h0.h[0] = __float2half_rn(v0.x);
        h0.h[1] = __float2half_rn(v0.y);
        h0.h[2] = __float2half_rn(v0.z);
        h0.h[3] = __float2half_rn(v0.w);
        h1.h[0] = __float2half_rn(v1.x);
        h1.h[1] = __float2half_rn(v1.y);
        h1.h[2] = __float2half_rn(v1.z);
        h1.h[3] = __float2half_rn(v1.w);
        *(uint2*)(sp + xrow0 * 80 + xq0 * 8) = h0.u;
        *(uint2*)(sp + xrow1 * 80 + xq1 * 8) = h1.u;
    };

    // ---- ldmatrix lane geometry (80B rows)
    uint32_t t8 = lane >> 3;
    uint32_t l7 = lane & 7;
    uint32_t arow[2], nrow[4];
#pragma unroll
    for (int i = 0; i < 2; i++)
        arow[i] = (wm * 32 + i * 16 + ((t8 & 1) << 3) + l7) * 80;
#pragma unroll
    for (int g = 0; g < 4; g++)
        nrow[g] = (wn * 64 + (g * 2 + (t8 >> 1)) * 8 + l7) * 80;
    uint32_t ka = (t8 >> 1) << 4;
    uint32_t kb_b = (t8 & 1) << 4;

    float acc[2][8][4];
#pragma unroll
    for (int i = 0; i < 2; i++)
#pragma unroll
        for (int j = 0; j < 8; j++)
#pragma unroll
            for (int r = 0; r < 4; r++) acc[i][j][r] = 0.f;

    // ---- prologue: fill stages 0,1
    {
        float4 v0, v1;
        issueW(0, sbase);
        loadX(0, v0, v1);
        storeX(smem, v0, v1);
        issueW(1, sbase + STG_SZ);
        loadX(1, v0, v1);
        storeX(smem + STG_SZ, v0, v1);
    }

    // ---- main loop (round-3 skeleton: 2 barriers per k-chunk)
    float4 pv0, pv1;
#pragma unroll 1
    for (int ck = 0; ck < 32; ck++) {
        if (ck == 31) asm volatile("cp.async.wait_group 0;" ::: "memory");
        else          asm volatile("cp.async.wait_group 1;" ::: "memory");
        __syncthreads();

        if (ck + 2 <= 31) loadX(ck + 2, pv0, pv1);

        uint32_t sb = sbase + (uint32_t)(ck & 1) * STG_SZ;
#pragma unroll
        for (int kf = 0; kf < 2; kf++) {
            uint32_t k16 = kf * 32;
            uint32_t bf[8][2];
#pragma unroll
            for (int g = 0; g < 4; g++) {
                uint32_t r0, r1, r2, r3;
                ldmx4(r0, r1, r2, r3, sb + OFF_W + nrow[g] + k16 + kb_b);
                bf[2 * g][0] = r0; bf[2 * g][1] = r1;
                bf[2 * g + 1][0] = r2; bf[2 * g + 1][1] = r3;
            }
            uint32_t a16[2][4];
#pragma unroll
            for (int i = 0; i < 2; i++)
                ldmx4(a16[i][0], a16[i][1], a16[i][2], a16[i][3], sb + arow[i] + k16 + ka);
#pragma unroll
            for (int i = 0; i < 2; i++)
#pragma unroll
                for (int j = 0; j < 8; j++)
                    mma_f16(acc[i][j], a16[i], bf[j]);
        }
        __syncthreads();

        if (ck + 2 <= 31) {
            storeX(smem + (ck & 1) * STG_SZ, pv0, pv1);
            issueW(ck + 2, sbase + (uint32_t)(ck & 1) * STG_SZ);
        }
    }

    // ---- epilogue: relu(acc + C) dot V, reduce to per-row scores
    float rs[4] = {0.f, 0.f, 0.f, 0.f};
#pragma unroll
    for (int i = 0; i < 2; i++) {
#pragma unroll
        for (int j = 0; j < 8; j++) {
            int c = wn * 64 + j * 8 + (lane & 3) * 2;
            float v0 = vs[c], v1 = vs[c + 1];
            float c0 = cs[c], c1 = cs[c + 1];
            rs[i * 2 + 0] += fmaxf(acc[i][j][0] + c0, 0.f) * v0
                           + fmaxf(acc[i][j][1] + c1, 0.f) * v1;
            rs[i * 2 + 1] += fmaxf(acc[i][j][2] + c0, 0.f) * v0
                           + fmaxf(acc[i][j][3] + c1, 0.f) * v1;
        }
    }
#pragma unroll
    for (int r = 0; r < 4; r++) {
        rs[r] += __shfl_xor_sync(0xffffffffu, rs[r], 1);
        rs[r] += __shfl_xor_sync(0xffffffffu, rs[r], 2);
    }
    float* scp = (float*)(smem + OFF_SCP);
    if ((lane & 3) == 0) {
        int row = wm * 32 + (lane >> 2);
        scp[wn * 128 + row + 0]  = rs[0];
        scp[wn * 128 + row + 8]  = rs[1];
        scp[wn * 128 + row + 16] = rs[2];
        scp[wn * 128 + row + 24] = rs[3];
    }
    __syncthreads();
    if (tid < 128) {
        float v = scp[tid] + scp[128 + tid] + scp[256 + tid] + scp[384 + tid];
        (ah ? g_sc1 : g_sc0)[b * Ss + s0 + tid] = v;
    }
}

// ---------------------------------------------------------------------------
// softmax over s<len of (g_sc0+g_sc1); prob -> out[B*H ...]
// ---------------------------------------------------------------------------
__global__ void softmax_kernel(const int* __restrict__ lengths, float* __restrict__ out) {
    int b = blockIdx.x;
    int len = lengths[b];
    int tid = threadIdx.x;
    const float* a0 = g_sc0 + b * Ss;
    const float* a1 = g_sc1 + b * Ss;
    float* prob = out + Bb * Hh + (size_t)b * Ss;

    __shared__ float red[8];
    __shared__ float s_m, s_sum;

    float m = -CUDART_INF_F;
    for (int s = tid; s < len; s += 256) m = fmaxf(m, a0[s] + a1[s]);
#pragma unroll
    for (int o = 16; o > 0; o >>= 1) m = fmaxf(m, __shfl_xor_sync(~0u, m, o));
    if ((tid & 31) == 0) red[tid >> 5] = m;
    __syncthreads();
    if (tid == 0) {
        float mm = red[0];
#pragma unroll
        for (int i = 1; i < 8; i++) mm = fmaxf(mm, red[i]);
        s_m = mm;
    }
    __syncthreads();
    m = s_m;

    float sum = 0.f;
    for (int s = tid; s < len; s += 256) sum += expf(a0[s] + a1[s] - m);
#pragma unroll
    for (int o = 16; o > 0; o >>= 1) sum += __shfl_xor_sync(~0u, sum, o);
    if ((tid & 31) == 0) red[tid >> 5] = sum;
    __syncthreads();
    if (tid == 0) {
        float ss = 0.f;
#pragma unroll
        for (int i = 0; i < 8; i++) ss += red[i];
        s_sum = ss;
    }
    __syncthreads();
    float inv = 1.f / s_sum;

    for (int s = tid; s < Ss; s += 256)
        prob[s] = (s < len) ? expf(a0[s] + a1[s] - m) * inv : 0.f;
}

// ---------------------------------------------------------------------------
// output pass, two-phase
// ---------------------------------------------------------------------------
__global__ void output_partial(const float* __restrict__ X,
                               const int* __restrict__ lengths,
                               const float* __restrict__ out) {
    int sc = blockIdx.x, b = blockIdx.y;
    int len = lengths[b];
    int s0 = sc * 128;
    if (s0 >= len) return;
    int n = min(128, len - s0);
    int tid = threadIdx.x;
    const float4* Xb = (const float4*)X + ((size_t)(b * Ss + s0)) * 256 + tid;
    const float* prob = out + Bb * Hh + (size_t)b * Ss + s0;
    float4 acc = make_float4(0.f, 0.f, 0.f, 0.f);
#pragma unroll 4
    for (int s = 0; s < n; s++) {
        float p = __ldg(prob + s);
        float4 x = Xb[(size_t)s * 256];
        acc.x = fmaf(p, x.x, acc.x);
        acc.y = fmaf(p, x.y, acc.y);
        acc.z = fmaf(p, x.z, acc.z);
        acc.w = fmaf(p, x.w, acc.w);
    }
    ((float4*)g_opart)[(b * 16 + sc) * 256 + tid] = acc;
}

__global__ void output_reduce(const int* __restrict__ lengths, float* __restrict__ out) {
    int b = blockIdx.x;
    int tid = threadIdx.x;
    int kmax = min(16, (lengths[b] + 127) >> 7);
    float4 acc = make_float4(0.f, 0.f, 0.f, 0.f);
    for (int c = 0; c < kmax; c++) {
        float4 v = ((const float4*)g_opart)[(b * 16 + c) * 256 + tid];
        acc.x += v.x; acc.y += v.y; acc.z += v.z; acc.w += v.w;
    }
    ((float4*)out)[b * 256 + tid] = acc;
}

// ---------------------------------------------------------------------------
extern "C" void kernel_launch(void* const* d_in, const int* in_sizes, int n_in,
                              void* d_out, int out_size) {
    const float* X   = (const float*)d_in[0];
    const float* x0  = (const float*)d_in[1];
    const float* x1  = (const float*)d_in[2];
    const float* x2  = (const float*)d_in[3];
    const int*   len = (const int*)  d_in[4];
    const float* WhW = (const float*)d_in[5];
    const float* WhB = (const float*)d_in[6];
    const float* W0  = (const float*)d_in[7];
    const float* W1  = (const float*)d_in[8];
    const float* W2  = (const float*)d_in[9];
    const float* V   = (const float*)d_in[10];
    float* out = (float*)d_out;

    static bool attr_done = false;
    if (!attr_done) {
        cudaFuncSetAttribute(scores_mma, cudaFuncAttributeMaxDynamicSharedMemorySize, SMEM_SZ);
        attr_done = true;
    }

    prep_w<<<512, 256>>>(WhW);
    ctx_kernel<<<Bb, 512>>>(x0, x1, x2, W0, W1, W2, WhB);
    scores_mma<<<dim3(16, 2, Bb), 512, SMEM_SZ>>>(X, V, len);
    softmax_kernel<<<Bb, 256>>>(len, out);
    output_partial<<<dim3(16, Bb), 256>>>(X, len, out);
    output_reduce<<<Bb, 256>>>(len, out);
}

// round 9
// speedup vs baseline: 2.6560x; 1.0970x over previous
#include <cuda_runtime.h>
#include <cuda_fp16.h>
#include <math_constants.h>
#include <cstdint>

#define Bb 64
#define Ss 2048
#define Hh 1024
#define Aa 512

// ---------------- device scratch (no allocation allowed) --------------------
__device__ float g_C[Bb * Aa];
__device__ float g_sc0[Bb * Ss];
__device__ float g_sc1[Bb * Ss];
__device__ float g_opart[Bb * 16 * Hh];
__device__ __half g_W16[Aa * Hh];

// ---------------- helpers ---------------------------------------------------
__device__ __forceinline__ uint32_t smem_u32(const void* p) {
    uint32_t a;
    asm("{ .reg .u64 t; cvta.to.shared.u64 t, %1; cvt.u32.u64 %0, t; }" : "=r"(a) : "l"(p));
    return a;
}
__device__ __forceinline__ void cp_async16(uint32_t dst, const void* src) {
    asm volatile("cp.async.cg.shared.global [%0], [%1], 16;" :: "r"(dst), "l"(src) : "memory");
}
__device__ __forceinline__ void cp_commit() {
    asm volatile("cp.async.commit_group;" ::: "memory");
}
__device__ __forceinline__ void ldmx4(uint32_t& r0, uint32_t& r1, uint32_t& r2, uint32_t& r3,
                                      uint32_t addr) {
    asm volatile("ldmatrix.sync.aligned.m8n8.x4.shared.b16 {%0,%1,%2,%3}, [%4];"
                 : "=r"(r0), "=r"(r1), "=r"(r2), "=r"(r3) : "r"(addr));
}
__device__ __forceinline__ void mma_f16(float* d, const uint32_t* a, const uint32_t* b) {
    asm volatile(
        "mma.sync.aligned.m16n8k16.row.col.f32.f16.f16.f32 "
        "{%0,%1,%2,%3}, {%4,%5,%6,%7}, {%8,%9}, {%0,%1,%2,%3};"
        : "+f"(d[0]), "+f"(d[1]), "+f"(d[2]), "+f"(d[3])
        : "r"(a[0]), "r"(a[1]), "r"(a[2]), "r"(a[3]), "r"(b[0]), "r"(b[1]));
}
__device__ __forceinline__ uint32_t pack_h2(float a, float b) {
    __half2 h = __float22half2_rn(make_float2(a, b));
    return *(uint32_t*)&h;
}

// smem: 2 stages of [X16 sub0 10240 | X16 sub1 10240 | W sub0 20480 | W sub1 20480]
// (80B rows; BK=64 per stage as two 32-wide sub-chunks)
#define STG_SZ   61440
#define OFF_XB   10240
#define OFF_WA   20480
#define OFF_WB   40960
#define OFF_SCP  122880           // 512 floats
#define OFF_CS   124928           // 256 floats
#define OFF_VS   125952           // 256 floats
#define SMEM_SZ  126976

// ---------------------------------------------------------------------------
// prep_w: round Wh (fp32 [512][1024]) to fp16, row-major single plane.
// ---------------------------------------------------------------------------
__global__ void prep_w(const float* __restrict__ Wh) {
    int a = blockIdx.x;
    int t = threadIdx.x;
    float4 v = *(const float4*)(Wh + (size_t)a * 1024 + t * 4);
    uint2 w;
    w.x = pack_h2(v.x, v.y);
    w.y = pack_h2(v.z, v.w);
    *(uint2*)(g_W16 + (size_t)a * 1024 + t * 4) = w;
}

// ---------------------------------------------------------------------------
// ctx: C[b,a] = Wh_b[a] + x0@W0[a] + x1@W1[a] + x2@W2[a]
// ---------------------------------------------------------------------------
__global__ void ctx_kernel(const float* __restrict__ x0,
                           const float* __restrict__ x1,
                           const float* __restrict__ x2,
                           const float* __restrict__ W0,
                           const float* __restrict__ W1,
                           const float* __restrict__ W2,
                           const float* __restrict__ Whb) {
    __shared__ float xs[2048];
    int b = blockIdx.x;
    int t = threadIdx.x;
    xs[t]        = x0[b * 1024 + t];
    xs[t + 512]  = x0[b * 1024 + t + 512];
    xs[1024 + t] = x1[b * 512 + t];
    xs[1536 + t] = x2[b * 512 + t];
    __syncthreads();
    int a = t;
    float acc = Whb[a];
    const float4* w0 = (const float4*)(W0 + (size_t)a * 1024);
    const float4* xv = (const float4*)xs;
#pragma unroll 8
    for (int i = 0; i < 256; i++) {
        float4 w = w0[i]; float4 x = xv[i];
        acc += w.x * x.x + w.y * x.y + w.z * x.z + w.w * x.w;
    }
    const float4* w1 = (const float4*)(W1 + (size_t)a * 512);
    const float4* x1v = (const float4*)(xs + 1024);
#pragma unroll 8
    for (int i = 0; i < 128; i++) {
        float4 w = w1[i]; float4 x = x1v[i];
        acc += w.x * x.x + w.y * x.y + w.z * x.z + w.w * x.w;
    }
    const float4* w2 = (const float4*)(W2 + (size_t)a * 512);
    const float4* x2v = (const float4*)(xs + 1536);
#pragma unroll 8
    for (int i = 0; i < 128; i++) {
        float4 w = w2[i]; float4 x = x2v[i];
        acc += w.x * x.x + w.y * x.y + w.z * x.z + w.w * x.w;
    }
    g_C[b * Aa + a] = acc;
}

// ---------------------------------------------------------------------------
// scores_mma: fused scores, single-pass fp16, BK=64 (16 k-iters, 32 barriers).
// grid (16 st, 2 ah, 64 b), 512 threads (16 warps 4x4), warp 32x64.
// ---------------------------------------------------------------------------
__global__ void __launch_bounds__(512)
scores_mma(const float* __restrict__ X,
           const float* __restrict__ V,
           const int* __restrict__ lengths) {
    extern __shared__ char smem[];
    int st = blockIdx.x, ah = blockIdx.y, b = blockIdx.z;
    int len = lengths[b];
    int s0 = st * 128;
    if (s0 >= len) return;

    int tid = threadIdx.x;
    int wid = tid >> 5;
    int lane = tid & 31;
    int wm = wid >> 2;
    int wn = wid & 3;

    float* cs = (float*)(smem + OFF_CS);
    float* vs = (float*)(smem + OFF_VS);
    if (tid < 256) {
        cs[tid] = g_C[b * Aa + ah * 256 + tid];
        vs[tid] = V[ah * 256 + tid];
    }

    uint32_t sbase = smem_u32(smem);

    // ---- X mapping: per sub-chunk, 2 slots of 8B per thread (1024 slots)
    int xrow0 = (tid * 2) >> 3;
    int xq0   = (tid * 2) & 7;
    int xrow1 = (tid * 2 + 1) >> 3;
    int xq1   = (tid * 2 + 1) & 7;
    const float* Xb = X + ((size_t)b * Ss + s0) * Hh;

    // ---- W cp.async mapping: per sub-chunk, 2 ops of 16B per thread
    const __half* wsrc[2];
    uint32_t wdst[2];
#pragma unroll
    for (int i = 0; i < 2; i++) {
        int l = tid * 2 + i;
        int row = l >> 2, ch = l & 3;
        wsrc[i] = g_W16 + ((size_t)(ah * 256 + row)) * Hh + ch * 8;
        wdst[i] = OFF_WA + row * 80 + ch * 16;
    }

    auto issueW = [&](int ck, uint32_t stage_u32) {
        int k0 = ck * 64;
#pragma unroll
        for (int i = 0; i < 2; i++) {
            cp_async16(stage_u32 + wdst[i], wsrc[i] + k0);
            cp_async16(stage_u32 + wdst[i] + (OFF_WB - OFF_WA), wsrc[i] + k0 + 32);
        }
        cp_commit();
    };
    auto loadX = [&](int ck, float4* v) {
        int k0 = ck * 64;
        v[0] = *(const float4*)(Xb + (size_t)xrow0 * Hh + k0 + xq0 * 4);
        v[1] = *(const float4*)(Xb + (size_t)xrow1 * Hh + k0 + xq1 * 4);
        v[2] = *(const float4*)(Xb + (size_t)xrow0 * Hh + k0 + 32 + xq0 * 4);
        v[3] = *(const float4*)(Xb + (size_t)xrow1 * Hh + k0 + 32 + xq1 * 4);
    };
    auto storeX = [&](char* sp, const float4* v) {
        uint2 p;
        p.x = pack_h2(v[0].x, v[0].y); p.y = pack_h2(v[0].z, v[0].w);
        *(uint2*)(sp + xrow0 * 80 + xq0 * 8) = p;
        p.x = pack_h2(v[1].x, v[1].y); p.y = pack_h2(v[1].z, v[1].w);
        *(uint2*)(sp + xrow1 * 80 + xq1 * 8) = p;
        p.x = pack_h2(v[2].x, v[2].y); p.y = pack_h2(v[2].z, v[2].w);
        *(uint2*)(sp + OFF_XB + xrow0 * 80 + xq0 * 8) = p;
        p.x = pack_h2(v[3].x, v[3].y); p.y = pack_h2(v[3].z, v[3].w);
        *(uint2*)(sp + OFF_XB + xrow1 * 80 + xq1 * 8) = p;
    };

    // ---- ldmatrix lane geometry (80B rows)
    uint32_t t8 = lane >> 3;
    uint32_t l7 = lane & 7;
    uint32_t arow[2], nrow[4];
#pragma unroll
    for (int i = 0; i < 2; i++)
        arow[i] = (wm * 32 + i * 16 + ((t8 & 1) << 3) + l7) * 80;
#pragma unroll
    for (int g = 0; g < 4; g++)
        nrow[g] = (wn * 64 + (g * 2 + (t8 >> 1)) * 8 + l7) * 80;
    uint32_t ka = (t8 >> 1) << 4;
    uint32_t kb_b = (t8 & 1) << 4;

    float acc[2][8][4];
#pragma unroll
    for (int i = 0; i < 2; i++)
#pragma unroll
        for (int j = 0; j < 8; j++)
#pragma unroll
            for (int r = 0; r < 4; r++) acc[i][j][r] = 0.f;

    // ---- prologue: fill stages 0,1
    {
        float4 v[4];
        issueW(0, sbase);
        loadX(0, v);
        storeX(smem, v);
        issueW(1, sbase + STG_SZ);
        loadX(1, v);
        storeX(smem + STG_SZ, v);
    }

    // ---- main loop: 16 k-iters of BK=64, 2 barriers each
    float4 pv[4];
#pragma unroll 1
    for (int ck = 0; ck < 16; ck++) {
        if (ck == 15) asm volatile("cp.async.wait_group 0;" ::: "memory");
        else          asm volatile("cp.async.wait_group 1;" ::: "memory");
        __syncthreads();

        if (ck + 2 <= 15) loadX(ck + 2, pv);

        uint32_t sb = sbase + (uint32_t)(ck & 1) * STG_SZ;
#pragma unroll
        for (int h = 0; h < 2; h++) {
            uint32_t Ab = sb + (uint32_t)h * OFF_XB;
            uint32_t Bbs = sb + OFF_WA + (uint32_t)h * (OFF_WB - OFF_WA);
#pragma unroll
            for (int kf = 0; kf < 2; kf++) {
                uint32_t k16 = kf * 32;
                uint32_t bf[8][2];
#pragma unroll
                for (int g = 0; g < 4; g++) {
                    uint32_t r0, r1, r2, r3;
                    ldmx4(r0, r1, r2, r3, Bbs + nrow[g] + k16 + kb_b);
                    bf[2 * g][0] = r0; bf[2 * g][1] = r1;
                    bf[2 * g + 1][0] = r2; bf[2 * g + 1][1] = r3;
                }
                uint32_t a16[2][4];
#pragma unroll
                for (int i = 0; i < 2; i++)
                    ldmx4(a16[i][0], a16[i][1], a16[i][2], a16[i][3], Ab + arow[i] + k16 + ka);
#pragma unroll
                for (int i = 0; i < 2; i++)
#pragma unroll
                    for (int j = 0; j < 8; j++)
                        mma_f16(acc[i][j], a16[i], bf[j]);
            }
        }
        __syncthreads();

        if (ck + 2 <= 15) {
            storeX(smem + (ck & 1) * STG_SZ, pv);
            issueW(ck + 2, sbase + (uint32_t)(ck & 1) * STG_SZ);
        }
    }

    // ---- epilogue: relu(acc + C) dot V, reduce to per-row scores
    float rs[4] = {0.f, 0.f, 0.f, 0.f};
#pragma unroll
    for (int i = 0; i < 2; i++) {
#pragma unroll
        for (int j = 0; j < 8; j++) {
            int c = wn * 64 + j * 8 + (lane & 3) * 2;
            float v0 = vs[c], v1 = vs[c + 1];
            float c0 = cs[c], c1 = cs[c + 1];
            rs[i * 2 + 0] += fmaxf(acc[i][j][0] + c0, 0.f) * v0
                           + fmaxf(acc[i][j][1] + c1, 0.f) * v1;
            rs[i * 2 + 1] += fmaxf(acc[i][j][2] + c0, 0.f) * v0
                           + fmaxf(acc[i][j][3] + c1, 0.f) * v1;
        }
    }
#pragma unroll
    for (int r = 0; r < 4; r++) {
        rs[r] += __shfl_xor_sync(0xffffffffu, rs[r], 1);
        rs[r] += __shfl_xor_sync(0xffffffffu, rs[r], 2);
    }
    float* scp = (float*)(smem + OFF_SCP);
    if ((lane & 3) == 0) {
        int row = wm * 32 + (lane >> 2);
        scp[wn * 128 + row + 0]  = rs[0];
        scp[wn * 128 + row + 8]  = rs[1];
        scp[wn * 128 + row + 16] = rs[2];
        scp[wn * 128 + row + 24] = rs[3];
    }
    __syncthreads();
    if (tid < 128) {
        float v = scp[tid] + scp[128 + tid] + scp[256 + tid] + scp[384 + tid];
        (ah ? g_sc1 : g_sc0)[b * Ss + s0 + tid] = v;
    }
}

// ---------------------------------------------------------------------------
// softmax over s<len of (g_sc0+g_sc1); prob -> out[B*H ...]
// ---------------------------------------------------------------------------
__global__ void softmax_kernel(const int* __restrict__ lengths, float* __restrict__ out) {
    int b = blockIdx.x;
    int len = lengths[b];
    int tid = threadIdx.x;
    const float* a0 = g_sc0 + b * Ss;
    const float* a1 = g_sc1 + b * Ss;
    float* prob = out + Bb * Hh + (size_t)b * Ss;

    __shared__ float red[8];
    __shared__ float s_m, s_sum;

    float m = -CUDART_INF_F;
    for (int s = tid; s < len; s += 256) m = fmaxf(m, a0[s] + a1[s]);
#pragma unroll
    for (int o = 16; o > 0; o >>= 1) m = fmaxf(m, __shfl_xor_sync(~0u, m, o));
    if ((tid & 31) == 0) red[tid >> 5] = m;
    __syncthreads();
    if (tid == 0) {
        float mm = red[0];
#pragma unroll
        for (int i = 1; i < 8; i++) mm = fmaxf(mm, red[i]);
        s_m = mm;
    }
    __syncthreads();
    m = s_m;

    float sum = 0.f;
    for (int s = tid; s < len; s += 256) sum += expf(a0[s] + a1[s] - m);
#pragma unroll
    for (int o = 16; o > 0; o >>= 1) sum += __shfl_xor_sync(~0u, sum, o);
    if ((tid & 31) == 0) red[tid >> 5] = sum;
    __syncthreads();
    if (tid == 0) {
        float ss = 0.f;
#pragma unroll
        for (int i = 0; i < 8; i++) ss += red[i];
        s_sum = ss;
    }
    __syncthreads();
    float inv = 1.f / s_sum;

    for (int s = tid; s < Ss; s += 256)
        prob[s] = (s < len) ? expf(a0[s] + a1[s] - m) * inv : 0.f;
}

// ---------------------------------------------------------------------------
// output pass, two-phase
// ---------------------------------------------------------------------------
__global__ void output_partial(const float* __restrict__ X,
                               const int* __restrict__ lengths,
                               const float* __restrict__ out) {
    int sc = blockIdx.x, b = blockIdx.y;
    int len = lengths[b];
    int s0 = sc * 128;
    if (s0 >= len) return;
    int n = min(128, len - s0);
    int tid = threadIdx.x;
    const float4* Xb = (const float4*)X + ((size_t)(b * Ss + s0)) * 256 + tid;
    const float* prob = out + Bb * Hh + (size_t)b * Ss + s0;
    float4 acc = make_float4(0.f, 0.f, 0.f, 0.f);
#pragma unroll 4
    for (int s = 0; s < n; s++) {
        float p = __ldg(prob + s);
        float4 x = Xb[(size_t)s * 256];
        acc.x = fmaf(p, x.x, acc.x);
        acc.y = fmaf(p, x.y, acc.y);
        acc.z = fmaf(p, x.z, acc.z);
        acc.w = fmaf(p, x.w, acc.w);
    }
    ((float4*)g_opart)[(b * 16 + sc) * 256 + tid] = acc;
}

__global__ void output_reduce(const int* __restrict__ lengths, float* __restrict__ out) {
    int b = blockIdx.x;
    int tid = threadIdx.x;
    int kmax = min(16, (lengths[b] + 127) >> 7);
    float4 acc = make_float4(0.f, 0.f, 0.f, 0.f);
    for (int c = 0; c < kmax; c++) {
        float4 v = ((const float4*)g_opart)[(b * 16 + c) * 256 + tid];
        acc.x += v.x; acc.y += v.y; acc.z += v.z; acc.w += v.w;
    }
    ((float4*)out)[b * 256 + tid] = acc;
}

// ---------------------------------------------------------------------------
extern "C" void kernel_launch(void* const* d_in, const int* in_sizes, int n_in,
                              void* d_out, int out_size) {
    const float* X   = (const float*)d_in[0];
    const float* x0  = (const float*)d_in[1];
    const float* x1  = (const float*)d_in[2];
    const float* x2  = (const float*)d_in[3];
    const int*   len = (const int*)  d_in[4];
    const float* WhW = (const float*)d_in[5];
    const float* WhB = (const float*)d_in[6];
    const float* W0  = (const float*)d_in[7];
    const float* W1  = (const float*)d_in[8];
    const float* W2  = (const float*)d_in[9];
    const float* V   = (const float*)d_in[10];
    float* out = (float*)d_out;

    static bool attr_done = false;
    if (!attr_done) {
        cudaFuncSetAttribute(scores_mma, cudaFuncAttributeMaxDynamicSharedMemorySize, SMEM_SZ);
        attr_done = true;
    }

    prep_w<<<512, 256>>>(WhW);
    ctx_kernel<<<Bb, 512>>>(x0, x1, x2, W0, W1, W2, WhB);
    scores_mma<<<dim3(16, 2, Bb), 512, SMEM_SZ>>>(X, V, len);
    softmax_kernel<<<Bb, 256>>>(len, out);
    output_partial<<<dim3(16, Bb), 256>>>(X, len, out);
    output_reduce<<<Bb, 256>>>(len, out);
}